// round 11
// baseline (speedup 1.0000x reference)
#include <cuda_runtime.h>

#define NB 4
#define NQ 128
#define NK 1024
#define HD 256
#define DV 256

// Scratch (device globals — no allocation allowed)
__device__ float g_qp[NB * NQ * HD];      // 512 KB projected queries
__device__ float g_kp[NB * NK * HD];      // 4 MB projected keys
__device__ float g_scores[NB * NQ * NK];  // 2 MB: UNNORMALIZED exp(score)
__device__ float g_rowsum[NB * NQ];       // per-row exp sums

__device__ __forceinline__ float tanh_fast(float x) {
    float y;
    asm("tanh.approx.f32 %0, %1;" : "=f"(y) : "f"(x));
    return y;
}

#define FFMA2(d, a, b, c) \
    asm("fma.rn.f32x2 %0, %1, %2, %3;" : "=l"(d) : "l"(a), "l"(b), "l"(c))
#define PACK2(d, lo, hi) \
    asm("mov.b64 %0, {%1, %2};" : "=l"(d) : "f"(lo), "f"(hi))
#define UNPACK2(lo, hi, d) \
    asm("mov.b64 {%0, %1}, %2;" : "=f"(lo), "=f"(hi) : "l"(d))

// -------------------------------------------------------------------------
// Fused projections: g_qp = Q @ Wq^T (grid.y 0..7), g_kp = K @ Wk^T (8..71).
// Block (0,0) also zero-inits g_rowsum (scores accumulates into it next).
// -------------------------------------------------------------------------
__global__ __launch_bounds__(256) void proj_kernel(
    const float* __restrict__ Q, const float* __restrict__ K,
    const float* __restrict__ Wq, const float* __restrict__ Wk,
    const int* __restrict__ valid_lens)
{
    __shared__ float Xt[16][68];   // [depth][row]
    __shared__ float Wt[16][68];   // [depth][col]

    const int by = blockIdx.y;

    if (by == 0 && blockIdx.x == 0) {
        g_rowsum[threadIdx.x] = 0.f;
        g_rowsum[threadIdx.x + 256] = 0.f;
    }

    const float* X;
    const float* W;
    float* out;
    int r0;
    if (by < 8) { X = Q; W = Wq; out = g_qp; r0 = by * 64; }
    else {
        const int t = by - 8;              // 0..63 over 4096 key rows
        const int b = t >> 4;              // batch
        const int k0l = (t & 15) * 64;     // key offset within batch
        if (k0l >= valid_lens[b]) return;  // dead keys: never read downstream
        X = K; W = Wk; out = g_kp; r0 = t * 64;
    }

    const int h0 = blockIdx.x * 64;
    const int tid = threadIdx.x;
    const int tx = tid & 15;
    const int ty = tid >> 4;

    const int lr = tid >> 2;        // 0..63
    const int lc = (tid & 3) * 4;   // 0,4,8,12

    unsigned long long acc2[4][2] = {};

    for (int d0 = 0; d0 < HD; d0 += 16) {
        float4 xv = *(const float4*)&X[(size_t)(r0 + lr) * HD + d0 + lc];
        float4 wt = *(const float4*)&W[(size_t)(h0 + lr) * HD + d0 + lc];
        Xt[lc + 0][lr] = xv.x; Xt[lc + 1][lr] = xv.y;
        Xt[lc + 2][lr] = xv.z; Xt[lc + 3][lr] = xv.w;
        Wt[lc + 0][lr] = wt.x; Wt[lc + 1][lr] = wt.y;
        Wt[lc + 2][lr] = wt.z; Wt[lc + 3][lr] = wt.w;
        __syncthreads();

        #pragma unroll
        for (int dd = 0; dd < 16; dd++) {
            float4 xr = *(const float4*)&Xt[dd][ty * 4];
            ulonglong2 w = *(const ulonglong2*)&Wt[dd][tx * 4];
            float xa[4] = {xr.x, xr.y, xr.z, xr.w};
            #pragma unroll
            for (int i = 0; i < 4; i++) {
                unsigned long long xb;
                PACK2(xb, xa[i], xa[i]);
                FFMA2(acc2[i][0], xb, w.x, acc2[i][0]);
                FFMA2(acc2[i][1], xb, w.y, acc2[i][1]);
            }
        }
        __syncthreads();
    }

    #pragma unroll
    for (int i = 0; i < 4; i++) {
        float o0, o1, o2, o3;
        UNPACK2(o0, o1, acc2[i][0]);
        UNPACK2(o2, o3, acc2[i][1]);
        *(float4*)&out[(size_t)(r0 + ty * 4 + i) * HD + h0 + tx * 4] =
            make_float4(o0, o1, o2, o3);
    }
}

// -------------------------------------------------------------------------
// Scores + exp + row-sum accumulation (softmax kernel eliminated).
// Writes exp(s) to g_scores and atomically adds per-row sums to g_rowsum.
// No max-subtraction needed: |s| <= sum|wv| (~13), exp safe in f32, and the
// max shift cancels exactly in the final division.
// blockIdx.x==0 blocks also zero this (b, q-block)'s output rows.
// Block: 128 threads (4 warps), 8 queries x 64 keys (16-key warp strips).
// Grid: (16, 16, 4) = 1024 blocks.
// -------------------------------------------------------------------------
__global__ __launch_bounds__(128) void scores_kernel(
    const float* __restrict__ wv, const int* __restrict__ valid_lens,
    float* __restrict__ out)
{
    const int b  = blockIdx.z;
    const int q0 = blockIdx.y * 8;
    const int k0 = blockIdx.x * 64;
    const int warp = threadIdx.x >> 5;
    const int lane = threadIdx.x & 31;
    const int hbase = lane * 8;

    // zero output rows for this (b, q-block) before av_kernel runs
    if (blockIdx.x == 0) {
        float* orow = out + (size_t)(b * NQ + q0) * DV;
        #pragma unroll
        for (int i = 0; i < 16; i++)
            orow[threadIdx.x + i * 128] = 0.f;
    }

    const int vlen = valid_lens[b];
    const int kw0 = k0 + warp * 16;
    int nit = vlen - kw0;
    if (nit <= 0) return;          // whole strip masked
    if (nit > 16) nit = 16;

    float qreg[8][8];
    const float* qbase = g_qp + (size_t)(b * NQ + q0) * HD + hbase;
    #pragma unroll
    for (int j = 0; j < 8; j++) {
        float4 a = *(const float4*)(qbase + j * HD);
        float4 c = *(const float4*)(qbase + j * HD + 4);
        qreg[j][0] = a.x; qreg[j][1] = a.y; qreg[j][2] = a.z; qreg[j][3] = a.w;
        qreg[j][4] = c.x; qreg[j][5] = c.y; qreg[j][6] = c.z; qreg[j][7] = c.w;
    }

    float wr[8];
    {
        float4 a = *(const float4*)(wv + hbase);
        float4 c = *(const float4*)(wv + hbase + 4);
        wr[0] = a.x; wr[1] = a.y; wr[2] = a.z; wr[3] = a.w;
        wr[4] = c.x; wr[5] = c.y; wr[6] = c.z; wr[7] = c.w;
    }

    const float* kbase = g_kp + (size_t)b * NK * HD + hbase;

    float4 ka = *(const float4*)(kbase + (size_t)kw0 * HD);
    float4 kc = *(const float4*)(kbase + (size_t)kw0 * HD + 4);

    float rsum = 0.f;              // lanes 0..7: running exp-sum for row q0+lane

    for (int it = 0; it < nit; it++) {
        float4 na, nc;
        if (it + 1 < nit) {
            const float* np = kbase + (size_t)(kw0 + it + 1) * HD;
            na = *(const float4*)np;
            nc = *(const float4*)(np + 4);
        }

        float kr[8] = {ka.x, ka.y, ka.z, ka.w, kc.x, kc.y, kc.z, kc.w};

        float acc[8];
        #pragma unroll
        for (int j = 0; j < 8; j++) {
            float s = 0.f;
            #pragma unroll
            for (int i = 0; i < 8; i++)
                s += wr[i] * tanh_fast(qreg[j][i] + kr[i]);
            acc[j] = s;
        }

        // full butterfly per j: afterwards every lane holds row-j's score
        #pragma unroll
        for (int j = 0; j < 8; j++) {
            #pragma unroll
            for (int off = 16; off; off >>= 1)
                acc[j] += __shfl_xor_sync(0xFFFFFFFFu, acc[j], off);
        }

        // route row-(lane) score to lanes 0..7 via a 7-SEL tree,
        // then ONE exp warp-instr + ONE store covers all 8 rows.
        float v01 = (lane & 1) ? acc[1] : acc[0];
        float v23 = (lane & 1) ? acc[3] : acc[2];
        float v45 = (lane & 1) ? acc[5] : acc[4];
        float v67 = (lane & 1) ? acc[7] : acc[6];
        float v03 = (lane & 2) ? v23 : v01;
        float v47 = (lane & 2) ? v67 : v45;
        float v   = (lane & 4) ? v47 : v03;

        float e = __expf(v);
        if (lane < 8) {
            g_scores[(size_t)(b * NQ + q0 + lane) * NK + kw0 + it] = e;
            rsum += e;
        }

        ka = na; kc = nc;
    }

    if (lane < 8)
        atomicAdd(&g_rowsum[b * NQ + q0 + lane], rsum);
}

// -------------------------------------------------------------------------
// AV GEMM with split-K on UNNORMALIZED exp-scores:
//   out[r][v] += (sum_k e[r][k] * V[b][k][v]) / rowsum[r]
// Ps entries at k >= vlen are masked to 0 on load (stale g_scores garbage).
// Tile: 32 rows x 64 vdims, K-chunk 64 (split-K=16), atomicAdd epilogue.
// Grid: (4, 16, 16) = 1024 blocks.
// -------------------------------------------------------------------------
__global__ __launch_bounds__(256) void av_kernel(
    const float* __restrict__ V, const int* __restrict__ valid_lens,
    float* __restrict__ out)
{
    __shared__ float Ps[32][17];
    __shared__ float Vs[16][68];

    const int v0 = blockIdx.x * 64;
    const int r0 = blockIdx.y * 32;          // global row (b*NQ + q)
    const int b  = r0 >> 7;
    const int kz = blockIdx.z * 64;

    const int vlen = valid_lens[b];
    if (kz >= vlen) return;                  // fully masked chunk

    const int tid = threadIdx.x;
    const int tx = tid & 15;
    const int ty = tid >> 4;                 // 0..15

    const int plr = (tid & 127) >> 2;        // 0..31
    const int plc = (tid & 3) * 4;           // 0,4,8,12
    const int vlr = tid >> 4;                // 0..15
    const int vlc = (tid & 15) * 4;          // 0..60

    const float* Vb = V + (size_t)b * NK * DV;

    float acc[2][4] = {};

    for (int k0 = kz; k0 < kz + 64; k0 += 16) {
        if (tid < 128) {
            float4 pv = *(const float4*)&g_scores[(size_t)(r0 + plr) * NK + k0 + plc];
            const int kb = k0 + plc;
            Ps[plr][plc + 0] = (kb + 0 < vlen) ? pv.x : 0.f;
            Ps[plr][plc + 1] = (kb + 1 < vlen) ? pv.y : 0.f;
            Ps[plr][plc + 2] = (kb + 2 < vlen) ? pv.z : 0.f;
            Ps[plr][plc + 3] = (kb + 3 < vlen) ? pv.w : 0.f;
        }
        float4 vv = *(const float4*)&Vb[(size_t)(k0 + vlr) * DV + v0 + vlc];
        Vs[vlr][vlc + 0] = vv.x; Vs[vlr][vlc + 1] = vv.y;
        Vs[vlr][vlc + 2] = vv.z; Vs[vlr][vlc + 3] = vv.w;
        __syncthreads();

        #pragma unroll
        for (int dd = 0; dd < 16; dd++) {
            float pr[2], vr[4];
            pr[0] = Ps[ty * 2 + 0][dd];
            pr[1] = Ps[ty * 2 + 1][dd];
            #pragma unroll
            for (int j = 0; j < 4; j++) vr[j] = Vs[dd][tx * 4 + j];
            #pragma unroll
            for (int i = 0; i < 2; i++)
                #pragma unroll
                for (int j = 0; j < 4; j++)
                    acc[i][j] += pr[i] * vr[j];
        }
        __syncthreads();
    }

    // scale each partial by 1/rowsum (distributes over split-K sum)
    const float inv0 = 1.0f / g_rowsum[r0 + ty * 2 + 0];
    const float inv1 = 1.0f / g_rowsum[r0 + ty * 2 + 1];

    #pragma unroll
    for (int j = 0; j < 4; j++) {
        atomicAdd(&out[(size_t)(r0 + ty * 2 + 0) * DV + v0 + tx * 4 + j],
                  acc[0][j] * inv0);
        atomicAdd(&out[(size_t)(r0 + ty * 2 + 1) * DV + v0 + tx * 4 + j],
                  acc[1][j] * inv1);
    }
}

// -------------------------------------------------------------------------
extern "C" void kernel_launch(void* const* d_in, const int* in_sizes, int n_in,
                              void* d_out, int out_size)
{
    const float* queries = (const float*)d_in[0];
    const float* keys    = (const float*)d_in[1];
    const float* values  = (const float*)d_in[2];
    const int*   vlens   = (const int*)d_in[3];
    const float* Wq      = (const float*)d_in[4];
    const float* Wk      = (const float*)d_in[5];
    const float* wv      = (const float*)d_in[6];
    float* out = (float*)d_out;

    // fused q+k projection + g_rowsum zero-init; dead k tiles skipped
    proj_kernel<<<dim3(4, 72), 256>>>(queries, keys, Wq, Wk, vlens);
    // scores -> exp + row sums (+ output zero-init); softmax kernel gone
    scores_kernel<<<dim3(16, 16, 4), 128>>>(wv, vlens, out);
    // AV GEMM on unnormalized exps, per-partial 1/rowsum scaling
    av_kernel<<<dim3(4, 16, 16), 256>>>(values, vlens, out);
}

// round 12
// speedup vs baseline: 1.5214x; 1.5214x over previous
#include <cuda_runtime.h>

#define NB 4
#define NQ 128
#define NK 1024
#define HD 256
#define DV 256

// Scratch (device globals — no allocation allowed)
__device__ float g_qp[NB * NQ * HD];      // 512 KB projected queries
__device__ float g_kp[NB * NK * HD];      // 4 MB projected keys
__device__ float g_scores[NB * NQ * NK];  // 2 MB scores -> probs (in place)

__device__ __forceinline__ float tanh_fast(float x) {
    float y;
    asm("tanh.approx.f32 %0, %1;" : "=f"(y) : "f"(x));
    return y;
}

#define FFMA2(d, a, b, c) \
    asm("fma.rn.f32x2 %0, %1, %2, %3;" : "=l"(d) : "l"(a), "l"(b), "l"(c))
#define PACK2(d, lo, hi) \
    asm("mov.b64 %0, {%1, %2};" : "=l"(d) : "f"(lo), "f"(hi))
#define UNPACK2(lo, hi, d) \
    asm("mov.b64 {%0, %1}, %2;" : "=f"(lo), "=f"(hi) : "l"(d))

// -------------------------------------------------------------------------
// Fused projections: g_qp = Q @ Wq^T (grid.y 0..7), g_kp = K @ Wk^T (8..71).
// Depth-major smem; packed fma.rn.f32x2 inner loop (proven neutral-or-better).
// Dead k-tiles (beyond valid_len) skipped.
// -------------------------------------------------------------------------
__global__ __launch_bounds__(256) void proj_kernel(
    const float* __restrict__ Q, const float* __restrict__ K,
    const float* __restrict__ Wq, const float* __restrict__ Wk,
    const int* __restrict__ valid_lens)
{
    __shared__ float Xt[16][68];   // [depth][row]
    __shared__ float Wt[16][68];   // [depth][col]

    const int by = blockIdx.y;
    const float* X;
    const float* W;
    float* out;
    int r0;
    if (by < 8) { X = Q; W = Wq; out = g_qp; r0 = by * 64; }
    else {
        const int t = by - 8;              // 0..63 over 4096 key rows
        const int b = t >> 4;              // batch
        const int k0l = (t & 15) * 64;     // key offset within batch
        if (k0l >= valid_lens[b]) return;  // dead keys: never read downstream
        X = K; W = Wk; out = g_kp; r0 = t * 64;
    }

    const int h0 = blockIdx.x * 64;
    const int tid = threadIdx.x;
    const int tx = tid & 15;
    const int ty = tid >> 4;

    const int lr = tid >> 2;        // 0..63
    const int lc = (tid & 3) * 4;   // 0,4,8,12

    unsigned long long acc2[4][2] = {};

    for (int d0 = 0; d0 < HD; d0 += 16) {
        float4 xv = *(const float4*)&X[(size_t)(r0 + lr) * HD + d0 + lc];
        float4 wt = *(const float4*)&W[(size_t)(h0 + lr) * HD + d0 + lc];
        Xt[lc + 0][lr] = xv.x; Xt[lc + 1][lr] = xv.y;
        Xt[lc + 2][lr] = xv.z; Xt[lc + 3][lr] = xv.w;
        Wt[lc + 0][lr] = wt.x; Wt[lc + 1][lr] = wt.y;
        Wt[lc + 2][lr] = wt.z; Wt[lc + 3][lr] = wt.w;
        __syncthreads();

        #pragma unroll
        for (int dd = 0; dd < 16; dd++) {
            float4 xr = *(const float4*)&Xt[dd][ty * 4];
            ulonglong2 w = *(const ulonglong2*)&Wt[dd][tx * 4];
            float xa[4] = {xr.x, xr.y, xr.z, xr.w};
            #pragma unroll
            for (int i = 0; i < 4; i++) {
                unsigned long long xb;
                PACK2(xb, xa[i], xa[i]);
                FFMA2(acc2[i][0], xb, w.x, acc2[i][0]);
                FFMA2(acc2[i][1], xb, w.y, acc2[i][1]);
            }
        }
        __syncthreads();
    }

    #pragma unroll
    for (int i = 0; i < 4; i++) {
        float o0, o1, o2, o3;
        UNPACK2(o0, o1, acc2[i][0]);
        UNPACK2(o2, o3, acc2[i][1]);
        *(float4*)&out[(size_t)(r0 + ty * 4 + i) * HD + h0 + tx * 4] =
            make_float4(o0, o1, o2, o3);
    }
}

// -------------------------------------------------------------------------
// Scores: s[b,q,k] = sum_h wv[h] * tanh(qp[b,q,h] + kp[b,k,h])
// f32 tanh (MUFU floor). Only k < valid_len[b] computed.
// Block: 128 threads (4 warps), 8 queries x 64 keys (16-key warp strips).
// Grid: (16, 16, 4) = 1024 blocks.
// -------------------------------------------------------------------------
__global__ __launch_bounds__(128) void scores_kernel(
    const float* __restrict__ wv, const int* __restrict__ valid_lens)
{
    const int b  = blockIdx.z;
    const int q0 = blockIdx.y * 8;
    const int k0 = blockIdx.x * 64;
    const int warp = threadIdx.x >> 5;
    const int lane = threadIdx.x & 31;
    const int hbase = lane * 8;

    const int vlen = valid_lens[b];
    const int kw0 = k0 + warp * 16;
    int nit = vlen - kw0;
    if (nit <= 0) return;          // whole strip masked
    if (nit > 16) nit = 16;

    float qreg[8][8];
    const float* qbase = g_qp + (size_t)(b * NQ + q0) * HD + hbase;
    #pragma unroll
    for (int j = 0; j < 8; j++) {
        float4 a = *(const float4*)(qbase + j * HD);
        float4 c = *(const float4*)(qbase + j * HD + 4);
        qreg[j][0] = a.x; qreg[j][1] = a.y; qreg[j][2] = a.z; qreg[j][3] = a.w;
        qreg[j][4] = c.x; qreg[j][5] = c.y; qreg[j][6] = c.z; qreg[j][7] = c.w;
    }

    float wr[8];
    {
        float4 a = *(const float4*)(wv + hbase);
        float4 c = *(const float4*)(wv + hbase + 4);
        wr[0] = a.x; wr[1] = a.y; wr[2] = a.z; wr[3] = a.w;
        wr[4] = c.x; wr[5] = c.y; wr[6] = c.z; wr[7] = c.w;
    }

    const float* kbase = g_kp + (size_t)b * NK * HD + hbase;

    float4 ka = *(const float4*)(kbase + (size_t)kw0 * HD);
    float4 kc = *(const float4*)(kbase + (size_t)kw0 * HD + 4);

    for (int it = 0; it < nit; it++) {
        float4 na, nc;
        if (it + 1 < nit) {
            const float* np = kbase + (size_t)(kw0 + it + 1) * HD;
            na = *(const float4*)np;
            nc = *(const float4*)(np + 4);
        }

        float kr[8] = {ka.x, ka.y, ka.z, ka.w, kc.x, kc.y, kc.z, kc.w};

        float acc[8];
        #pragma unroll
        for (int j = 0; j < 8; j++) {
            float s = 0.f;
            #pragma unroll
            for (int i = 0; i < 8; i++)
                s += wr[i] * tanh_fast(qreg[j][i] + kr[i]);
            acc[j] = s;
        }

        #pragma unroll
        for (int j = 0; j < 8; j++) {
            float v = acc[j];
            v += __shfl_xor_sync(0xFFFFFFFFu, v, 16);
            v += __shfl_xor_sync(0xFFFFFFFFu, v, 8);
            v += __shfl_xor_sync(0xFFFFFFFFu, v, 4);
            v += __shfl_xor_sync(0xFFFFFFFFu, v, 2);
            v += __shfl_xor_sync(0xFFFFFFFFu, v, 1);
            if (lane == 0)
                g_scores[(size_t)(b * NQ + q0 + j) * NK + kw0 + it] = v;
        }

        ka = na; kc = nc;
    }
}

// -------------------------------------------------------------------------
// Masked softmax over each 1024-long score row, in place.
// Also zeroes this row's 256-float output slice (AV accumulates atomically).
// One 256-thread block per row. Grid: NB*NQ = 512 blocks.
// -------------------------------------------------------------------------
__global__ __launch_bounds__(256) void softmax_kernel(
    const int* __restrict__ valid_lens, float* __restrict__ out)
{
    __shared__ float red[8];

    const int row = blockIdx.x;             // 0..511
    const int b   = row >> 7;
    const int tid = threadIdx.x;
    const int warp = tid >> 5;
    const int lane = tid & 31;
    const int vlen = valid_lens[b];

    // zero this row's output slice (before av_kernel runs)
    out[(size_t)row * DV + tid] = 0.f;

    float* rp = g_scores + (size_t)row * NK + tid * 4;

    float4 v = *(const float4*)rp;
    const int kb = tid * 4;
    if (kb + 0 >= vlen) v.x = -1e6f;
    if (kb + 1 >= vlen) v.y = -1e6f;
    if (kb + 2 >= vlen) v.z = -1e6f;
    if (kb + 3 >= vlen) v.w = -1e6f;

    float mx = fmaxf(fmaxf(v.x, v.y), fmaxf(v.z, v.w));
    #pragma unroll
    for (int off = 16; off; off >>= 1)
        mx = fmaxf(mx, __shfl_xor_sync(0xFFFFFFFFu, mx, off));
    if (lane == 0) red[warp] = mx;
    __syncthreads();
    if (warp == 0) {
        float m = red[lane & 7];
        #pragma unroll
        for (int off = 4; off; off >>= 1)
            m = fmaxf(m, __shfl_xor_sync(0xFFFFFFFFu, m, off));
        if (lane == 0) red[0] = m;
    }
    __syncthreads();
    mx = red[0];
    __syncthreads();

    float4 e;
    e.x = __expf(v.x - mx); e.y = __expf(v.y - mx);
    e.z = __expf(v.z - mx); e.w = __expf(v.w - mx);
    float sum = e.x + e.y + e.z + e.w;
    #pragma unroll
    for (int off = 16; off; off >>= 1)
        sum += __shfl_xor_sync(0xFFFFFFFFu, sum, off);
    if (lane == 0) red[warp] = sum;
    __syncthreads();
    if (warp == 0) {
        float s = red[lane & 7];
        #pragma unroll
        for (int off = 4; off; off >>= 1)
            s += __shfl_xor_sync(0xFFFFFFFFu, s, off);
        if (lane == 0) red[0] = s;
    }
    __syncthreads();
    const float inv = 1.0f / red[0];

    e.x *= inv; e.y *= inv; e.z *= inv; e.w *= inv;
    *(float4*)rp = e;
}

// -------------------------------------------------------------------------
// AV GEMM with split-K, DOUBLE-BUFFERED smem pipeline:
// prefetch stage s+1 into registers during compute of stage s; one sync
// per stage instead of two; LDG latency hidden under 256 FFMA-cycles.
// Tile: 32 rows x 64 vdims, K-chunk 64 (split-K=16), atomicAdd epilogue.
// Grid: (4, 16, 16) = 1024 blocks.
// -------------------------------------------------------------------------
__global__ __launch_bounds__(256) void av_kernel(
    const float* __restrict__ V, const int* __restrict__ valid_lens,
    float* __restrict__ out)
{
    __shared__ float Ps[2][32][17];
    __shared__ float Vs[2][16][68];

    const int v0 = blockIdx.x * 64;
    const int r0 = blockIdx.y * 32;          // global row (b*NQ + q)
    const int b  = r0 >> 7;
    const int kz = blockIdx.z * 64;

    if (kz >= valid_lens[b]) return;         // probs exactly zero here

    const int tid = threadIdx.x;
    const int tx = tid & 15;
    const int ty = tid >> 4;                 // 0..15

    const int plr = (tid & 127) >> 2;        // 0..31
    const int plc = (tid & 3) * 4;           // 0,4,8,12
    const int vlr = tid >> 4;                // 0..15
    const int vlc = (tid & 15) * 4;          // 0..60

    const float* Vb = V + (size_t)b * NK * DV;

    float acc[2][4] = {};

    // prologue: load stage 0 into buffer 0
    float4 pv, vv;
    if (tid < 128)
        pv = *(const float4*)&g_scores[(size_t)(r0 + plr) * NK + kz + plc];
    vv = *(const float4*)&Vb[(size_t)(kz + vlr) * DV + v0 + vlc];
    if (tid < 128) {
        Ps[0][plr][plc + 0] = pv.x; Ps[0][plr][plc + 1] = pv.y;
        Ps[0][plr][plc + 2] = pv.z; Ps[0][plr][plc + 3] = pv.w;
    }
    Vs[0][vlr][vlc + 0] = vv.x; Vs[0][vlr][vlc + 1] = vv.y;
    Vs[0][vlr][vlc + 2] = vv.z; Vs[0][vlr][vlc + 3] = vv.w;
    __syncthreads();

    #pragma unroll
    for (int s = 0; s < 4; s++) {
        const int buf = s & 1;

        // prefetch stage s+1 into registers (overlapped with compute)
        if (s < 3) {
            const int kn = kz + (s + 1) * 16;
            if (tid < 128)
                pv = *(const float4*)&g_scores[(size_t)(r0 + plr) * NK + kn + plc];
            vv = *(const float4*)&Vb[(size_t)(kn + vlr) * DV + v0 + vlc];
        }

        // compute stage s from smem[buf]
        #pragma unroll
        for (int dd = 0; dd < 16; dd++) {
            float pr[2], vr[4];
            pr[0] = Ps[buf][ty * 2 + 0][dd];
            pr[1] = Ps[buf][ty * 2 + 1][dd];
            #pragma unroll
            for (int j = 0; j < 4; j++) vr[j] = Vs[buf][dd][tx * 4 + j];
            #pragma unroll
            for (int i = 0; i < 2; i++)
                #pragma unroll
                for (int j = 0; j < 4; j++)
                    acc[i][j] += pr[i] * vr[j];
        }

        // commit prefetch to the other buffer; single sync per stage
        if (s < 3) {
            const int nb = buf ^ 1;
            if (tid < 128) {
                Ps[nb][plr][plc + 0] = pv.x; Ps[nb][plr][plc + 1] = pv.y;
                Ps[nb][plr][plc + 2] = pv.z; Ps[nb][plr][plc + 3] = pv.w;
            }
            Vs[nb][vlr][vlc + 0] = vv.x; Vs[nb][vlr][vlc + 1] = vv.y;
            Vs[nb][vlr][vlc + 2] = vv.z; Vs[nb][vlr][vlc + 3] = vv.w;
            __syncthreads();
        }
    }

    #pragma unroll
    for (int i = 0; i < 2; i++)
        #pragma unroll
        for (int j = 0; j < 4; j++)
            atomicAdd(&out[(size_t)(r0 + ty * 2 + i) * DV + v0 + tx * 4 + j],
                      acc[i][j]);
}

// -------------------------------------------------------------------------
extern "C" void kernel_launch(void* const* d_in, const int* in_sizes, int n_in,
                              void* d_out, int out_size)
{
    const float* queries = (const float*)d_in[0];
    const float* keys    = (const float*)d_in[1];
    const float* values  = (const float*)d_in[2];
    const int*   vlens   = (const int*)d_in[3];
    const float* Wq      = (const float*)d_in[4];
    const float* Wk      = (const float*)d_in[5];
    const float* wv      = (const float*)d_in[6];
    float* out = (float*)d_out;

    // fused q+k projection; dead k tiles skipped
    proj_kernel<<<dim3(4, 72), 256>>>(queries, keys, Wq, Wk, vlens);
    // scores (f32 tanh, only k < valid_len)
    scores_kernel<<<dim3(16, 16, 4), 128>>>(wv, vlens);
    // masked softmax (in place) + zero output rows
    softmax_kernel<<<512, 256>>>(vlens, out);
    // AV GEMM, split-K=16, double-buffered pipeline
    av_kernel<<<dim3(4, 16, 16), 256>>>(values, vlens, out);
}